// round 15
// baseline (speedup 1.0000x reference)
#include <cuda_runtime.h>
#include <cuda_fp16.h>
#include <cstdint>

// Problem constants
#define BATCH    1024
#define NLAYER   2
#define KTRI     32
#define NFAC     4
#define HID      64             // N
#define KDIM     128            // K = 2*DIM
#define APAD     136            // A row stride (halves): 272 B -> ldmatrix conflict-free
#define BPAD     72             // B row stride (halves): 144 B -> ldmatrix conflict-free
#define NTILES   (BATCH * 2 * NLAYER)   // 4096
#define GRID     608                     // 4 CTAs/SM * 152 SMs (persistent)

// ---- shared memory layout (bytes) ----
#define OFF_A      0                          // fp16 A [128][136] = 34816
#define OFF_B      34816                      // fp16 W1 [128][72] = 18432
#define OFF_B1     53248                      // 64 f
#define OFF_W2     53504                      // 64 f
#define OFF_LOG    53760                      // 2*128 f = 1024 (N-half partial logits)
#define SMEM_BYTES 54784                      // 4 x 54784 = 214 KB <= 228 KB -> occ 4

__device__ __forceinline__ uint32_t smem_u32(const void* p) {
    uint32_t a;
    asm("{ .reg .u64 t; cvta.to.shared.u64 t, %1; cvt.u32.u64 %0, t; }" : "=r"(a) : "l"(p));
    return a;
}
__device__ __forceinline__ void ldsm_x4(uint32_t& r0, uint32_t& r1, uint32_t& r2,
                                        uint32_t& r3, uint32_t addr) {
    asm volatile("ldmatrix.sync.aligned.m8n8.x4.shared.b16 {%0,%1,%2,%3}, [%4];"
                 : "=r"(r0), "=r"(r1), "=r"(r2), "=r"(r3) : "r"(addr));
}
__device__ __forceinline__ void ldsm_x4t(uint32_t& r0, uint32_t& r1, uint32_t& r2,
                                         uint32_t& r3, uint32_t addr) {
    asm volatile("ldmatrix.sync.aligned.m8n8.x4.trans.shared.b16 {%0,%1,%2,%3}, [%4];"
                 : "=r"(r0), "=r"(r1), "=r"(r2), "=r"(r3) : "r"(addr));
}
__device__ __forceinline__ void mma16816(float* c, uint32_t a0, uint32_t a1,
                                         uint32_t a2, uint32_t a3,
                                         uint32_t b0, uint32_t b1) {
    asm volatile(
        "mma.sync.aligned.m16n8k16.row.col.f32.f16.f16.f32 "
        "{%0,%1,%2,%3}, {%4,%5,%6,%7}, {%8,%9}, {%0,%1,%2,%3};"
        : "+f"(c[0]), "+f"(c[1]), "+f"(c[2]), "+f"(c[3])
        : "r"(a0), "r"(a1), "r"(a2), "r"(a3), "r"(b0), "r"(b1));
}

// Load this warp's 8 triple indices for a tile (lanes 0-7): slot base s,
// head (lanes 0-3) / tail (lanes 4-7), k = s + (lid&3).
__device__ __forceinline__ int load_idx8(const int* __restrict__ users_triple,
                                         const int* __restrict__ items_triple,
                                         int tile, int s, int lid)
{
    if (lid >= 8) return 0;
    const int b     = tile & (BATCH - 1);
    const int tw    = (tile >> 10) & 1;
    const int layer = tile >> 11;
    const int* trip = tw ? items_triple : users_triple;
    const int c = (lid < 4) ? 0 : 2;
    const int k = s + (lid & 3);
    return trip[(((long)b * 3 + c) * NLAYER + layer) * KTRI + k];
}

__global__ void __launch_bounds__(256, 4)
kgat_pers8_kernel(const float* __restrict__ node_emb,
                  const float* __restrict__ W1,
                  const float* __restrict__ b1,
                  const float* __restrict__ W2,
                  const int*   __restrict__ users,
                  const int*   __restrict__ items,
                  const int*   __restrict__ users_triple,
                  const int*   __restrict__ items_triple,
                  float*       __restrict__ out)
{
    extern __shared__ char smem[];
    __half* a_sh   = reinterpret_cast<__half*>(smem + OFF_A);
    __half* bW_sh  = reinterpret_cast<__half*>(smem + OFF_B);
    float*  b1_sh  = reinterpret_cast<float*>(smem + OFF_B1);
    float*  w2_sh  = reinterpret_cast<float*>(smem + OFF_W2);
    float*  lp_sh  = reinterpret_cast<float*>(smem + OFF_LOG);  // [2][128]

    const int tid = threadIdx.x;
    const int wid = tid >> 5;
    const int lid = tid & 31;
    const int pm  = wid >> 1;          // m-pair 0..3 -> rows pm*32..+31
    const int nh  = wid & 1;           // n-half 0..1 -> cols nh*32..+31
    const int s   = pm * 8 + nh * 4;   // triple-slot base for this warp's gather

    // ---- stage W1 (fp32->fp16 direct from gmem) + b1/W2, once per CTA ----
    #pragma unroll 4
    for (int i = tid; i < KDIM * HID; i += 256) {
        const int k = i >> 6, n = i & 63;          // coalesced read of W1[k][n]
        bW_sh[k * BPAD + n] = __float2half_rn(W1[i]);
    }
    if (tid < 64) { b1_sh[tid] = b1[tid]; w2_sh[tid] = W2[tid]; }
    __syncthreads();

    const float4* ne4 = reinterpret_cast<const float4*>(node_emb);
    const uint32_t a_u = smem_u32(smem + OFF_A);
    const uint32_t b_u = smem_u32(smem + OFF_B);
    const int g   = lid >> 2;
    const int tig = lid & 3;

    // ldmatrix base addresses (lane constants)
    const uint32_t a_addr0 = a_u +
        (uint32_t)(((pm * 32 + (lid & 15)) * APAD + (lid >> 4) * 8) * 2);
    const uint32_t b_addr0 = b_u +
        (uint32_t)(((lid & 15) * BPAD + nh * 32 + (lid >> 4) * 8) * 2);

    // gather store lane constants (warp's 16 rows start at wid*16 = pm*32+nh*16)
    const int d4     = (lid & 15) * 4;
    const int dst_p0 = (lid >> 4) * APAD + d4;          // parity 0: f = 0 + (lid>>4)
    const int dst_p1 = (2 + (lid >> 4)) * APAD + d4;    // parity 1: f = 2 + (lid>>4)
    __half* a_w = a_sh + wid * 16 * APAD;

    int tile = blockIdx.x;
    int idx_pref = (tile < NTILES)
        ? load_idx8(users_triple, items_triple, tile, s, lid) : 0;

    for (; tile < NTILES; tile += GRID) {
        const int b     = tile & (BATCH - 1);
        const int tw    = (tile >> 10) & 1;
        const int layer = tile >> 11;
        const int idx   = idx_pref;

        // ---- origin copy (layer-0 tiles) ----
        if (layer == 0) {
            const int* idxv = tw ? items : users;
            const long org = (long)idxv[b];
            out[(((long)tw * 3 + 0) * BATCH + b) * 256 + tid] =
                node_emb[org * 256 + tid];
        }

        // ---- broadcast the 8 node base offsets once (uint32 float4 units) ----
        uint32_t nodeoff[8];
        #pragma unroll
        for (int r = 0; r < 8; ++r)
            nodeoff[r] = (uint32_t)__shfl_sync(0xffffffffu, idx, r) * 64u;

        // ---- warp-local gather in four 4-deep LDG batches ----
        #pragma unroll
        for (int qb = 0; qb < 4; ++qb) {
            float4 v[4];
            #pragma unroll
            for (int j = 0; j < 4; ++j) {          // 4 LDG.128 in flight
                const int it = qb * 4 + j;
                const int r = it >> 1;
                const int p = it & 1;
                v[j] = ne4[nodeoff[r] + (uint32_t)(p * 32 + lid)];
            }
            #pragma unroll
            for (int j = 0; j < 4; ++j) {          // convert + STS
                const int it = qb * 4 + j;
                const int r = it >> 1;
                const int p = it & 1;
                const int off = (r & 3) * 4 * APAD + (r < 4 ? 0 : 64)
                              + (p ? dst_p1 : dst_p0);
                __half2 p0 = __floats2half2_rn(v[j].x, v[j].y);
                __half2 p1 = __floats2half2_rn(v[j].z, v[j].w);
                uint2 u;
                u.x = *reinterpret_cast<uint32_t*>(&p0);
                u.y = *reinterpret_cast<uint32_t*>(&p1);
                *reinterpret_cast<uint2*>(&a_w[off]) = u;
            }
        }

        // ---- prefetch next tile's indices (hidden under MMA) ----
        {
            const int nt_ = tile + GRID;
            idx_pref = (nt_ < NTILES)
                ? load_idx8(users_triple, items_triple, nt_, s, lid) : 0;
        }

        // pair barrier: warps 2pm and 2pm+1 exchange their 16-row halves
        asm volatile("bar.sync %0, 64;" :: "r"(pm + 1) : "memory");

        // ---- HMMA GEMM: warp computes rows pm*32..+31, cols nh*32..+31 ----
        float acc[2][4][4];
        #pragma unroll
        for (int mt = 0; mt < 2; ++mt)
            #pragma unroll
            for (int nt = 0; nt < 4; ++nt)
                #pragma unroll
                for (int j = 0; j < 4; ++j) acc[mt][nt][j] = 0.f;

        #pragma unroll
        for (int ks = 0; ks < 8; ++ks) {
            uint32_t am[2][4];
            #pragma unroll
            for (int mt = 0; mt < 2; ++mt)
                ldsm_x4(am[mt][0], am[mt][1], am[mt][2], am[mt][3],
                        a_addr0 + (uint32_t)((mt * 16 * APAD + ks * 16) * 2));
            const uint32_t bk = b_addr0 + (uint32_t)(ks * 16 * BPAD * 2);
            #pragma unroll
            for (int pr = 0; pr < 2; ++pr) {
                uint32_t b0, b1, b2, b3;
                ldsm_x4t(b0, b1, b2, b3, bk + (uint32_t)(pr * 16 * 2));
                #pragma unroll
                for (int mt = 0; mt < 2; ++mt) {
                    mma16816(acc[mt][pr * 2],     am[mt][0], am[mt][1],
                             am[mt][2], am[mt][3], b0, b1);
                    mma16816(acc[mt][pr * 2 + 1], am[mt][0], am[mt][1],
                             am[mt][2], am[mt][3], b2, b3);
                }
            }
        }

        // ---- N-half partial logits: relu(D+b1).W2 over this warp's 32 cols ----
        {
            float pl[2][2] = {{0.f, 0.f}, {0.f, 0.f}};
            #pragma unroll
            for (int mt = 0; mt < 2; ++mt) {
                #pragma unroll
                for (int nt = 0; nt < 4; ++nt) {
                    #pragma unroll
                    for (int j = 0; j < 2; ++j) {
                        const int col = nh * 32 + nt * 8 + tig * 2 + j;
                        const float bb = b1_sh[col];
                        const float ww = w2_sh[col];
                        pl[mt][0] += fmaxf(acc[mt][nt][j]     + bb, 0.f) * ww;
                        pl[mt][1] += fmaxf(acc[mt][nt][2 + j] + bb, 0.f) * ww;
                    }
                }
            }
            #pragma unroll
            for (int mt = 0; mt < 2; ++mt) {
                pl[mt][0] += __shfl_xor_sync(0xffffffffu, pl[mt][0], 1);
                pl[mt][0] += __shfl_xor_sync(0xffffffffu, pl[mt][0], 2);
                pl[mt][1] += __shfl_xor_sync(0xffffffffu, pl[mt][1], 1);
                pl[mt][1] += __shfl_xor_sync(0xffffffffu, pl[mt][1], 2);
            }
            if (tig == 0) {
                float* dst = lp_sh + nh * 128 + pm * 32;
                dst[g]      = pl[0][0];
                dst[8 + g]  = pl[0][1];
                dst[16 + g] = pl[1][0];
                dst[24 + g] = pl[1][1];
            }
        }
        __syncthreads();

        // ---- softmax + weighted sum on all 8 warps (f = pm) ----
        {
            const int f = pm;
            const int d = nh * 32 + lid;
            const int row = lid * NFAC + f;           // lane holds k = lid
            float lg = lp_sh[row] + lp_sh[128 + row];
            float m = lg;
            #pragma unroll
            for (int off = 16; off; off >>= 1)
                m = fmaxf(m, __shfl_xor_sync(0xffffffffu, m, off));
            const float e = __expf(lg - m);
            float sm = e;
            #pragma unroll
            for (int off = 16; off; off >>= 1)
                sm += __shfl_xor_sync(0xffffffffu, sm, off);
            const float w = e / sm;

            float a = 0.f;
            #pragma unroll
            for (int k = 0; k < KTRI; ++k) {
                const float wk = __shfl_sync(0xffffffffu, w, k);
                const float tv = __half2float(a_sh[(k * NFAC + f) * APAD + 64 + d]);
                a = fmaf(wk, tv, a);
            }
            out[(((long)tw * 3 + 1 + layer) * BATCH + b) * 256 + f * 64 + d] = a;
        }
        __syncthreads();   // protect A/lp_sh before next tile overwrites
    }
}

extern "C" void kernel_launch(void* const* d_in, const int* in_sizes, int n_in,
                              void* d_out, int out_size)
{
    const float* node_emb = (const float*)d_in[0];
    const float* W1       = (const float*)d_in[2];
    const float* b1       = (const float*)d_in[3];
    const float* W2       = (const float*)d_in[4];
    const int*   users    = (const int*)d_in[6];
    const int*   items    = (const int*)d_in[7];
    const int*   utrip    = (const int*)d_in[8];
    const int*   itrip    = (const int*)d_in[9];
    float* out = (float*)d_out;

    cudaFuncSetAttribute(kgat_pers8_kernel,
                         cudaFuncAttributeMaxDynamicSharedMemorySize, SMEM_BYTES);

    kgat_pers8_kernel<<<GRID, 256, SMEM_BYTES>>>(node_emb, W1, b1, W2,
                                                 users, items, utrip, itrip, out);
}

// round 16
// speedup vs baseline: 1.2555x; 1.2555x over previous
#include <cuda_runtime.h>
#include <cuda_fp16.h>
#include <cstdint>

// Problem constants
#define BATCH    1024
#define NLAYER   2
#define KTRI     32
#define NFAC     4
#define HID      64             // N
#define KDIM     128            // K = 2*DIM
#define APAD     136            // A row stride (halves): 272 B -> ldmatrix conflict-free
#define BPAD     72             // B row stride (halves): 144 B -> ldmatrix conflict-free
#define NTILES   (BATCH * 2 * NLAYER)   // 4096
#define GRID     456                     // 3 CTAs/SM * 152 SMs (persistent)

// ---- shared memory layout (bytes) ----
#define OFF_A      0                          // fp16 A [128][136] = 34816
#define OFF_B      34816                      // fp16 W1 [128][72] = 18432
#define OFF_B1     53248                      // 64 f
#define OFF_W2     53504                      // 64 f
#define OFF_LOG    53760                      // 2*128 f = 1024 (N-half partial logits)
#define SMEM_BYTES 54784                      // -> 3 CTAs/SM

__device__ __forceinline__ uint32_t smem_u32(const void* p) {
    uint32_t a;
    asm("{ .reg .u64 t; cvta.to.shared.u64 t, %1; cvt.u32.u64 %0, t; }" : "=r"(a) : "l"(p));
    return a;
}
__device__ __forceinline__ void ldsm_x4(uint32_t& r0, uint32_t& r1, uint32_t& r2,
                                        uint32_t& r3, uint32_t addr) {
    asm volatile("ldmatrix.sync.aligned.m8n8.x4.shared.b16 {%0,%1,%2,%3}, [%4];"
                 : "=r"(r0), "=r"(r1), "=r"(r2), "=r"(r3) : "r"(addr));
}
__device__ __forceinline__ void ldsm_x4t(uint32_t& r0, uint32_t& r1, uint32_t& r2,
                                         uint32_t& r3, uint32_t addr) {
    asm volatile("ldmatrix.sync.aligned.m8n8.x4.trans.shared.b16 {%0,%1,%2,%3}, [%4];"
                 : "=r"(r0), "=r"(r1), "=r"(r2), "=r"(r3) : "r"(addr));
}
__device__ __forceinline__ void mma16816(float* c, uint32_t a0, uint32_t a1,
                                         uint32_t a2, uint32_t a3,
                                         uint32_t b0, uint32_t b1) {
    asm volatile(
        "mma.sync.aligned.m16n8k16.row.col.f32.f16.f16.f32 "
        "{%0,%1,%2,%3}, {%4,%5,%6,%7}, {%8,%9}, {%0,%1,%2,%3};"
        : "+f"(c[0]), "+f"(c[1]), "+f"(c[2]), "+f"(c[3])
        : "r"(a0), "r"(a1), "r"(a2), "r"(a3), "r"(b0), "r"(b1));
}

// Load this warp's 8 triple indices for a tile (lanes 0-7): slot base s,
// head (lanes 0-3) / tail (lanes 4-7), k = s + (lid&3).
__device__ __forceinline__ int load_idx8(const int* __restrict__ users_triple,
                                         const int* __restrict__ items_triple,
                                         int tile, int s, int lid)
{
    if (lid >= 8) return 0;
    const int b     = tile & (BATCH - 1);
    const int tw    = (tile >> 10) & 1;
    const int layer = tile >> 11;
    const int* trip = tw ? items_triple : users_triple;
    const int c = (lid < 4) ? 0 : 2;
    const int k = s + (lid & 3);
    return trip[(((long)b * 3 + c) * NLAYER + layer) * KTRI + k];
}

__global__ void __launch_bounds__(256, 3)
kgat_pers9_kernel(const float* __restrict__ node_emb,
                  const float* __restrict__ W1,
                  const float* __restrict__ b1,
                  const float* __restrict__ W2,
                  const int*   __restrict__ users,
                  const int*   __restrict__ items,
                  const int*   __restrict__ users_triple,
                  const int*   __restrict__ items_triple,
                  float*       __restrict__ out)
{
    extern __shared__ char smem[];
    __half* a_sh   = reinterpret_cast<__half*>(smem + OFF_A);
    __half* bW_sh  = reinterpret_cast<__half*>(smem + OFF_B);
    float*  b1_sh  = reinterpret_cast<float*>(smem + OFF_B1);
    float*  w2_sh  = reinterpret_cast<float*>(smem + OFF_W2);
    float*  lp_sh  = reinterpret_cast<float*>(smem + OFF_LOG);  // [2][128]

    const int tid = threadIdx.x;
    const int wid = tid >> 5;
    const int lid = tid & 31;
    const int pm  = wid >> 1;          // m-pair 0..3 -> rows pm*32..+31
    const int nh  = wid & 1;           // n-half 0..1 -> cols nh*32..+31
    const int s   = pm * 8 + nh * 4;   // triple-slot base for this warp's gather

    // ---- stage W1 (fp32->fp16 direct from gmem) + b1/W2, once per CTA ----
    #pragma unroll 4
    for (int i = tid; i < KDIM * HID; i += 256) {
        const int k = i >> 6, n = i & 63;          // coalesced read of W1[k][n]
        bW_sh[k * BPAD + n] = __float2half_rn(W1[i]);
    }
    if (tid < 64) { b1_sh[tid] = b1[tid]; w2_sh[tid] = W2[tid]; }
    __syncthreads();

    const float4* ne4 = reinterpret_cast<const float4*>(node_emb);
    const uint32_t a_u = smem_u32(smem + OFF_A);
    const uint32_t b_u = smem_u32(smem + OFF_B);
    const int g   = lid >> 2;
    const int tig = lid & 3;

    // ldmatrix base addresses (lane constants)
    const uint32_t a_addr0 = a_u +
        (uint32_t)(((pm * 32 + (lid & 15)) * APAD + (lid >> 4) * 8) * 2);
    const uint32_t b_addr0 = b_u +
        (uint32_t)(((lid & 15) * BPAD + nh * 32 + (lid >> 4) * 8) * 2);

    // gather store lane constants (warp's 16 rows start at wid*16 = pm*32+nh*16)
    const int d4     = (lid & 15) * 4;
    const int dst_p0 = (lid >> 4) * APAD + d4;          // parity 0: f = 0 + (lid>>4)
    const int dst_p1 = (2 + (lid >> 4)) * APAD + d4;    // parity 1: f = 2 + (lid>>4)
    __half* a_w = a_sh + wid * 16 * APAD;

    int tile = blockIdx.x;
    int idx_pref = (tile < NTILES)
        ? load_idx8(users_triple, items_triple, tile, s, lid) : 0;

    for (; tile < NTILES; tile += GRID) {
        const int b     = tile & (BATCH - 1);
        const int tw    = (tile >> 10) & 1;
        const int layer = tile >> 11;
        const int idx   = idx_pref;

        // ---- origin copy (layer-0 tiles) ----
        if (layer == 0) {
            const int* idxv = tw ? items : users;
            const long org = (long)idxv[b];
            out[(((long)tw * 3 + 0) * BATCH + b) * 256 + tid] =
                node_emb[org * 256 + tid];
        }

        // ---- broadcast the 8 node base offsets once ----
        long nodeoff[8];
        #pragma unroll
        for (int r = 0; r < 8; ++r)
            nodeoff[r] = (long)__shfl_sync(0xffffffffu, idx, r) * 64;

        // ---- warp-local gather in two 8-deep LDG batches (high MLP) ----
        #pragma unroll
        for (int half = 0; half < 2; ++half) {
            float4 v[8];
            #pragma unroll
            for (int j = 0; j < 8; ++j) {          // 8 LDG.128 in flight
                const int it = half * 8 + j;
                const int r = it >> 1;
                const int p = it & 1;
                v[j] = ne4[nodeoff[r] + p * 32 + lid];
            }
            #pragma unroll
            for (int j = 0; j < 8; ++j) {          // convert + STS
                const int it = half * 8 + j;
                const int r = it >> 1;
                const int p = it & 1;
                const int off = (r & 3) * 4 * APAD + (r < 4 ? 0 : 64)
                              + (p ? dst_p1 : dst_p0);
                __half2 p0 = __floats2half2_rn(v[j].x, v[j].y);
                __half2 p1 = __floats2half2_rn(v[j].z, v[j].w);
                uint2 u;
                u.x = *reinterpret_cast<uint32_t*>(&p0);
                u.y = *reinterpret_cast<uint32_t*>(&p1);
                *reinterpret_cast<uint2*>(&a_w[off]) = u;
            }
        }

        // ---- prefetch next tile's indices (hidden under MMA) ----
        {
            const int nt_ = tile + GRID;
            idx_pref = (nt_ < NTILES)
                ? load_idx8(users_triple, items_triple, nt_, s, lid) : 0;
        }

        // pair barrier: warps 2pm and 2pm+1 exchange their 16-row halves
        asm volatile("bar.sync %0, 64;" :: "r"(pm + 1) : "memory");

        // ---- HMMA GEMM: warp computes rows pm*32..+31, cols nh*32..+31 ----
        float acc[2][4][4];
        #pragma unroll
        for (int mt = 0; mt < 2; ++mt)
            #pragma unroll
            for (int nt = 0; nt < 4; ++nt)
                #pragma unroll
                for (int j = 0; j < 4; ++j) acc[mt][nt][j] = 0.f;

        #pragma unroll
        for (int ks = 0; ks < 8; ++ks) {
            uint32_t am[2][4];
            #pragma unroll
            for (int mt = 0; mt < 2; ++mt)
                ldsm_x4(am[mt][0], am[mt][1], am[mt][2], am[mt][3],
                        a_addr0 + (uint32_t)((mt * 16 * APAD + ks * 16) * 2));
            const uint32_t bk = b_addr0 + (uint32_t)(ks * 16 * BPAD * 2);
            #pragma unroll
            for (int pr = 0; pr < 2; ++pr) {
                uint32_t b0, b1, b2, b3;
                ldsm_x4t(b0, b1, b2, b3, bk + (uint32_t)(pr * 16 * 2));
                #pragma unroll
                for (int mt = 0; mt < 2; ++mt) {
                    mma16816(acc[mt][pr * 2],     am[mt][0], am[mt][1],
                             am[mt][2], am[mt][3], b0, b1);
                    mma16816(acc[mt][pr * 2 + 1], am[mt][0], am[mt][1],
                             am[mt][2], am[mt][3], b2, b3);
                }
            }
        }

        // ---- N-half partial logits: relu(D+b1).W2 over this warp's 32 cols ----
        {
            float pl[2][2] = {{0.f, 0.f}, {0.f, 0.f}};
            #pragma unroll
            for (int mt = 0; mt < 2; ++mt) {
                #pragma unroll
                for (int nt = 0; nt < 4; ++nt) {
                    #pragma unroll
                    for (int j = 0; j < 2; ++j) {
                        const int col = nh * 32 + nt * 8 + tig * 2 + j;
                        const float bb = b1_sh[col];
                        const float ww = w2_sh[col];
                        pl[mt][0] += fmaxf(acc[mt][nt][j]     + bb, 0.f) * ww;
                        pl[mt][1] += fmaxf(acc[mt][nt][2 + j] + bb, 0.f) * ww;
                    }
                }
            }
            #pragma unroll
            for (int mt = 0; mt < 2; ++mt) {
                pl[mt][0] += __shfl_xor_sync(0xffffffffu, pl[mt][0], 1);
                pl[mt][0] += __shfl_xor_sync(0xffffffffu, pl[mt][0], 2);
                pl[mt][1] += __shfl_xor_sync(0xffffffffu, pl[mt][1], 1);
                pl[mt][1] += __shfl_xor_sync(0xffffffffu, pl[mt][1], 2);
            }
            if (tig == 0) {
                float* dst = lp_sh + nh * 128 + pm * 32;
                dst[g]      = pl[0][0];
                dst[8 + g]  = pl[0][1];
                dst[16 + g] = pl[1][0];
                dst[24 + g] = pl[1][1];
            }
        }
        __syncthreads();

        // ---- softmax + weighted sum: warps 0-3, f = wid, half2 d-pairs ----
        if (wid < 4) {
            const int f = wid;
            const int row = lid * NFAC + f;           // lane holds k = lid
            float lg = lp_sh[row] + lp_sh[128 + row];
            float m = lg;
            #pragma unroll
            for (int off = 16; off; off >>= 1)
                m = fmaxf(m, __shfl_xor_sync(0xffffffffu, m, off));
            const float e = __expf(lg - m);
            float sm = e;
            #pragma unroll
            for (int off = 16; off; off >>= 1)
                sm += __shfl_xor_sync(0xffffffffu, sm, off);
            const float w = e / sm;

            float ax = 0.f, ay = 0.f;
            #pragma unroll
            for (int k = 0; k < KTRI; ++k) {
                const float wk = __shfl_sync(0xffffffffu, w, k);
                const __half2 tv = *reinterpret_cast<const __half2*>(
                    &a_sh[(k * NFAC + f) * APAD + 64 + 2 * lid]);
                const float2 tf = __half22float2(tv);
                ax = fmaf(wk, tf.x, ax);
                ay = fmaf(wk, tf.y, ay);
            }
            float2 res = make_float2(ax, ay);
            *reinterpret_cast<float2*>(
                &out[(((long)tw * 3 + 1 + layer) * BATCH + b) * 256
                     + f * 64 + 2 * lid]) = res;
        }
        __syncthreads();   // protect A/lp_sh before next tile overwrites
    }
}

extern "C" void kernel_launch(void* const* d_in, const int* in_sizes, int n_in,
                              void* d_out, int out_size)
{
    const float* node_emb = (const float*)d_in[0];
    const float* W1       = (const float*)d_in[2];
    const float* b1       = (const float*)d_in[3];
    const float* W2       = (const float*)d_in[4];
    const int*   users    = (const int*)d_in[6];
    const int*   items    = (const int*)d_in[7];
    const int*   utrip    = (const int*)d_in[8];
    const int*   itrip    = (const int*)d_in[9];
    float* out = (float*)d_out;

    cudaFuncSetAttribute(kgat_pers9_kernel,
                         cudaFuncAttributeMaxDynamicSharedMemorySize, SMEM_BYTES);

    kgat_pers9_kernel<<<GRID, 256, SMEM_BYTES>>>(node_emb, W1, b1, W2,
                                                 users, items, utrip, itrip, out);
}